// round 1
// baseline (speedup 1.0000x reference)
#include <cuda_runtime.h>
#include <math.h>

// Problem constants
#define NB   16
#define LL   512
#define DD   256
#define FF   256
#define TT   4096
#define MM   (NB * LL)        // 8192 rows
#define KTOT 768              // D * 3
#define EPS  1e-5f

// ---------------- scratch (static device globals; no allocs) ----------------
__device__ float g_h1[MM * FF];
__device__ float g_h2[MM * FF];
__device__ float g_w1t[3 * DD * FF];   // [k][d][f]
__device__ float g_w2t[3 * FF * FF];
__device__ int   g_cum[NB * LL];

// ---------------- weight transpose: (F,D,K) -> (K,D,F) ----------------------
__global__ void transpose_w_kernel(const float* __restrict__ w1,
                                   const float* __restrict__ w2) {
    int i = blockIdx.x * 256 + threadIdx.x;   // over 3*256*256 = 196608
    if (i >= 3 * DD * FF) return;
    int f = i & 255;
    int d = (i >> 8) & 255;
    int k = i >> 16;
    g_w1t[i] = w1[f * KTOT + d * 3 + k];
    g_w2t[i] = w2[f * KTOT + d * 3 + k];
}

// ---------------- conv-as-GEMM: C[m,f] = sum_{k,d} A[n, l+k-1, d] * Wt[k,d,f] + bias[f]
// A: [16,512,256] row-major. Wt: [3][256][256]. C: [8192,256].
#define BM 128
#define BN 128
#define BK 16
__global__ __launch_bounds__(256, 1)
void conv_gemm_kernel(const float* __restrict__ A,
                      const float* __restrict__ Wt,
                      const float* __restrict__ bias,
                      float* __restrict__ C) {
    __shared__ float As[BK][BM + 4];
    __shared__ float Bs[BK][BN];

    const int bm = blockIdx.x * BM;
    const int bn = blockIdx.y * BN;
    const int tid = threadIdx.x;
    const int tx = tid & 15;     // 0..15  -> col group
    const int ty = tid >> 4;     // 0..15  -> row group

    // A-load mapping: 512 float4 slots per iter (128 rows x 4 quads)
    const int colq = tid & 3;    // which float4 along kk
    const int rowa = tid >> 2;   // 0..63, rows rowa and rowa+64
    // B-load mapping: 512 float4 slots (16 kk x 32 f-quads)
    const int fq = tid & 31;     // f quad
    const int kb = tid >> 5;     // 0..7, kk rows kb and kb+8

    float acc[8][8];
#pragma unroll
    for (int i = 0; i < 8; i++)
#pragma unroll
        for (int j = 0; j < 8; j++) acc[i][j] = 0.f;

#pragma unroll 1
    for (int kt = 0; kt < KTOT / BK; ++kt) {
        const int kk0 = kt * BK;
        const int k = kk0 >> 8;        // constant within chunk (256 % 16 == 0)
        const int dbase = kk0 & 255;

        // ---- load A tile (im2col with shift k-1) ----
#pragma unroll
        for (int r = 0; r < 2; ++r) {
            int row = rowa + r * 64;
            int m = bm + row;
            int n = m >> 9;
            int l = m & 511;
            int lsrc = l + k - 1;
            float4 v = make_float4(0.f, 0.f, 0.f, 0.f);
            if (lsrc >= 0 && lsrc < LL)
                v = *(const float4*)(A + ((n << 9) + lsrc) * DD + dbase + colq * 4);
            As[colq * 4 + 0][row] = v.x;
            As[colq * 4 + 1][row] = v.y;
            As[colq * 4 + 2][row] = v.z;
            As[colq * 4 + 3][row] = v.w;
        }
        // ---- load B tile (coalesced from transposed weights) ----
#pragma unroll
        for (int r = 0; r < 2; ++r) {
            int kkl = kb + r * 8;
            float4 v = *(const float4*)(Wt + (k << 16) + (dbase + kkl) * FF + bn + fq * 4);
            *(float4*)&Bs[kkl][fq * 4] = v;
        }
        __syncthreads();

#pragma unroll
        for (int kkl = 0; kkl < BK; ++kkl) {
            float a[8], b[8];
#pragma unroll
            for (int i = 0; i < 8; i++) a[i] = As[kkl][ty * 8 + i];
#pragma unroll
            for (int j = 0; j < 8; j++) b[j] = Bs[kkl][tx * 8 + j];
#pragma unroll
            for (int i = 0; i < 8; i++)
#pragma unroll
                for (int j = 0; j < 8; j++) acc[i][j] = fmaf(a[i], b[j], acc[i][j]);
        }
        __syncthreads();
    }

    // epilogue: add bias, store (float4)
    float4 bv0 = *(const float4*)(bias + bn + tx * 8);
    float4 bv1 = *(const float4*)(bias + bn + tx * 8 + 4);
#pragma unroll
    for (int i = 0; i < 8; i++) {
        int row = bm + ty * 8 + i;
        float* cp = C + row * FF + bn + tx * 8;
        float4 o0 = make_float4(acc[i][0] + bv0.x, acc[i][1] + bv0.y,
                                acc[i][2] + bv0.z, acc[i][3] + bv0.w);
        float4 o1 = make_float4(acc[i][4] + bv1.x, acc[i][5] + bv1.y,
                                acc[i][6] + bv1.z, acc[i][7] + bv1.w);
        *(float4*)cp = o0;
        *(float4*)(cp + 4) = o1;
    }
}

// ---------------- LayerNorm(F=256) + ReLU, in place ----------------
__global__ void ln_relu_kernel(float* __restrict__ h,
                               const float* __restrict__ g,
                               const float* __restrict__ b) {
    int row = blockIdx.x;
    int t = threadIdx.x;
    float v = h[row * FF + t];
    float s1 = v, s2 = v * v;
#pragma unroll
    for (int o = 16; o; o >>= 1) {
        s1 += __shfl_xor_sync(0xffffffffu, s1, o);
        s2 += __shfl_xor_sync(0xffffffffu, s2, o);
    }
    __shared__ float r1[8], r2[8];
    int w = t >> 5, ln = t & 31;
    if (ln == 0) { r1[w] = s1; r2[w] = s2; }
    __syncthreads();
    float m1 = 0.f, m2 = 0.f;
#pragma unroll
    for (int i = 0; i < 8; i++) { m1 += r1[i]; m2 += r2[i]; }
    float mean = m1 * (1.f / 256.f);
    float var = m2 * (1.f / 256.f) - mean * mean;
    float y = (v - mean) * rsqrtf(var + EPS) * g[t] + b[t];
    h[row * FF + t] = fmaxf(y, 0.f);
}

// ---------------- final linear + relu -> dpo ----------------
__global__ void linear_relu_kernel(const float* __restrict__ h,
                                   const float* __restrict__ lw,
                                   const float* __restrict__ lb,
                                   float* __restrict__ dpo) {
    int warp = threadIdx.x >> 5, lane = threadIdx.x & 31;
    int row = blockIdx.x * 8 + warp;
    const float* hp = h + row * FF;
    float s = 0.f;
#pragma unroll
    for (int j = 0; j < 8; j++) s = fmaf(hp[lane + j * 32], lw[lane + j * 32], s);
#pragma unroll
    for (int o = 16; o; o >>= 1) s += __shfl_xor_sync(0xffffffffu, s, o);
    if (lane == 0) dpo[row] = fmaxf(s + lb[0], 0.f);
}

// ---------------- per-n inclusive cumsum of target ----------------
__global__ void cumsum_kernel(const int* __restrict__ target) {
    int n = blockIdx.x, t = threadIdx.x;   // 512 threads
    __shared__ int s[LL];
    s[t] = target[n * LL + t];
    __syncthreads();
#pragma unroll
    for (int off = 1; off < LL; off <<= 1) {
        int v = (t >= off) ? s[t - off] : 0;
        __syncthreads();
        s[t] += v;
        __syncthreads();
    }
    g_cum[n * LL + t] = s[t];
}

// ---------------- length regulation: gather + zero-fill ----------------
__global__ void length_reg_kernel(const float* __restrict__ x,
                                  float* __restrict__ out) {
    unsigned tidg = blockIdx.x * 256u + threadIdx.x;  // over 16*4096*64 float4
    int c4 = tidg & 63;
    int t = (tidg >> 6) & 4095;
    int n = tidg >> 18;
    const int* cn = g_cum + n * LL;
    int total = __ldg(cn + LL - 1);
    float4 v = make_float4(0.f, 0.f, 0.f, 0.f);
    if (t < total) {
        int lo = 0, hi = LL;
        while (lo < hi) {
            int mid = (lo + hi) >> 1;
            if (__ldg(cn + mid) > t) hi = mid; else lo = mid + 1;
        }
        v = *(const float4*)(x + ((n << 9) + lo) * DD + c4 * 4);
    }
    *(float4*)(out + (size_t)tidg * 4) = v;
}

// ---------------- launch ----------------
extern "C" void kernel_launch(void* const* d_in, const int* in_sizes, int n_in,
                              void* d_out, int out_size) {
    const float* x   = (const float*)d_in[0];
    const float* c1w = (const float*)d_in[1];
    const float* c1b = (const float*)d_in[2];
    const float* g1  = (const float*)d_in[3];
    const float* b1  = (const float*)d_in[4];
    const float* c2w = (const float*)d_in[5];
    const float* c2b = (const float*)d_in[6];
    const float* g2  = (const float*)d_in[7];
    const float* b2  = (const float*)d_in[8];
    const float* lw  = (const float*)d_in[9];
    const float* lb  = (const float*)d_in[10];
    const int*   tgt = (const int*)d_in[11];

    float* out = (float*)d_out;                         // [16,4096,256]
    float* dpo = out + (size_t)NB * TT * DD;            // [16,512]

    float *h1, *h2, *w1t, *w2t;
    cudaGetSymbolAddress((void**)&h1, g_h1);
    cudaGetSymbolAddress((void**)&h2, g_h2);
    cudaGetSymbolAddress((void**)&w1t, g_w1t);
    cudaGetSymbolAddress((void**)&w2t, g_w2t);

    // duration predictor chain
    transpose_w_kernel<<<768, 256>>>(c1w, c2w);
    {
        dim3 grid(MM / BM, FF / BN);
        conv_gemm_kernel<<<grid, 256>>>(x, w1t, c1b, h1);
        ln_relu_kernel<<<MM, 256>>>(h1, g1, b1);
        conv_gemm_kernel<<<grid, 256>>>(h1, w2t, c2b, h2);
        ln_relu_kernel<<<MM, 256>>>(h2, g2, b2);
        linear_relu_kernel<<<MM / 8, 256>>>(h2, lw, lb, dpo);
    }
    // length regulation chain
    cumsum_kernel<<<NB, LL>>>(tgt);
    length_reg_kernel<<<(NB * TT * (DD / 4)) / 256, 256>>>(x, out);
}

// round 3
// speedup vs baseline: 1.9411x; 1.9411x over previous
#include <cuda_runtime.h>
#include <cuda_bf16.h>
#include <cstdint>
#include <math.h>

// Problem constants
#define NB   16
#define LL   512
#define DD   256
#define FF   256
#define TT   4096
#define MM   (NB * LL)        // 8192 rows
#define KTOT 768              // D * 3
#define EPS  1e-5f

// ---------------- scratch (static device globals; no allocs) ----------------
__device__ __align__(16) float g_h1[MM * FF];
__device__ __align__(16) __nv_bfloat16 g_b1hi[FF * KTOT];
__device__ __align__(16) __nv_bfloat16 g_b1lo[FF * KTOT];
__device__ __align__(16) __nv_bfloat16 g_b2hi[FF * KTOT];
__device__ __align__(16) __nv_bfloat16 g_b2lo[FF * KTOT];
__device__ int   g_cum[NB * LL];

// ============== weight prep: split w (F,D,K) -> Bhi/Blo [F][k*256+d] =========
__global__ void prep_b_kernel(const float* __restrict__ w1,
                              const float* __restrict__ w2) {
    int i = blockIdx.x * 256 + threadIdx.x;     // over 256*768
    if (i >= FF * KTOT) return;
    int f = i / KTOT;
    int kf = i - f * KTOT;
    int k = kf >> 8;
    int d = kf & 255;
    float v1 = w1[f * KTOT + d * 3 + k];
    float v2 = w2[f * KTOT + d * 3 + k];
    __nv_bfloat16 h1 = __float2bfloat16_rn(v1);
    __nv_bfloat16 h2 = __float2bfloat16_rn(v2);
    g_b1hi[i] = h1;
    g_b1lo[i] = __float2bfloat16_rn(v1 - __bfloat162float(h1));
    g_b2hi[i] = h2;
    g_b2lo[i] = __float2bfloat16_rn(v2 - __bfloat162float(h2));
}

// ============== fused conv(K=3) GEMM + LayerNorm + ReLU (+ linear) ==========
// Per CTA: 64 rows (one l-chunk of one sequence) x 256 output channels.
// 512 threads = 16 warps, warp grid 2(m) x 8(n), warp tile 32x32.
// K loop: 24 chunks of 32 (3 taps x 8 d-chunks), bf16 hi/lo 3-pass HMMA.

// smem byte offsets (dynamic)
#define ST_BYTES   51200            // one stage: Ahi|Alo|Bhi|Blo
#define OFF_AHI    0                // 64 rows x 80B
#define OFF_ALO    5120
#define OFF_BHI    10240            // 256 rows x 80B
#define OFF_BLO    30720
#define OFF_PART_S (2 * ST_BYTES)           // 8 x 64 floats
#define OFF_PART_Q (OFF_PART_S + 2048)
#define OFF_MEAN   (OFF_PART_Q + 2048)      // 64 floats
#define OFF_RSTD   (OFF_MEAN + 256)
#define SMEM_CONV  (OFF_RSTD + 256)

__device__ __forceinline__ void hmma(float* d, const uint32_t* a, const uint32_t* b) {
    asm volatile(
        "mma.sync.aligned.m16n8k16.row.col.f32.bf16.bf16.f32 "
        "{%0,%1,%2,%3}, {%4,%5,%6,%7}, {%8,%9}, {%0,%1,%2,%3};"
        : "+f"(d[0]), "+f"(d[1]), "+f"(d[2]), "+f"(d[3])
        : "r"(a[0]), "r"(a[1]), "r"(a[2]), "r"(a[3]), "r"(b[0]), "r"(b[1]));
}

__device__ __forceinline__ uint32_t pack2(float a, float b) {
    __nv_bfloat162 t = __floats2bfloat162_rn(a, b);
    return *reinterpret_cast<uint32_t*>(&t);
}

template <bool DO_LIN>
__global__ __launch_bounds__(512, 1)
void conv_fused_kernel(const float* __restrict__ A,
                       const __nv_bfloat16* __restrict__ Bhi,
                       const __nv_bfloat16* __restrict__ Blo,
                       const float* __restrict__ bias,
                       const float* __restrict__ gam,
                       const float* __restrict__ bet,
                       const float* __restrict__ lw,
                       const float* __restrict__ lb,
                       float* __restrict__ out)   // h1 if !DO_LIN, dpo if DO_LIN
{
    extern __shared__ char smem[];
    const int tid = threadIdx.x;
    const int wid = tid >> 5;
    const int lane = tid & 31;
    const int g = lane >> 2;          // groupID
    const int t4 = lane & 3;          // thread-in-group
    const int wm = wid >> 3;          // 0..1
    const int wn = wid & 7;           // 0..7
    const int bm = blockIdx.x * 64;
    const int n = bm >> 9;
    const int l0 = bm & 511;

    // prefetch register sets
    float4 aval;
    uint4  bhv[2], blv[2];
    // A load mapping: row = tid>>3 (0..63), kq = tid&7 (float4 along d)
    const int arow = tid >> 3;
    const int akq = tid & 7;
    // B load mapping: slots tid and tid+512 over 1024 uint4 per buffer
    const int brow0 = tid >> 2, bkq0 = tid & 3;
    const int brow1 = (tid + 512) >> 2, bkq1 = tid & 3;

    auto prefetch = [&](int c) {
        const int tap = c >> 3;
        const int dc = (c & 7) * 32;
        int lsrc = l0 + arow + tap - 1;
        aval = make_float4(0.f, 0.f, 0.f, 0.f);
        if (lsrc >= 0 && lsrc < LL)
            aval = *(const float4*)(A + (size_t)((n << 9) + lsrc) * DD + dc + akq * 4);
        const int kfb = tap * 256 + dc;
        bhv[0] = *(const uint4*)(Bhi + (size_t)brow0 * KTOT + kfb + bkq0 * 8);
        bhv[1] = *(const uint4*)(Bhi + (size_t)brow1 * KTOT + kfb + bkq1 * 8);
        blv[0] = *(const uint4*)(Blo + (size_t)brow0 * KTOT + kfb + bkq0 * 8);
        blv[1] = *(const uint4*)(Blo + (size_t)brow1 * KTOT + kfb + bkq1 * 8);
    };

    auto store_stage = [&](int s) {
        char* stg = smem + s * ST_BYTES;
        __nv_bfloat16 hx = __float2bfloat16_rn(aval.x);
        __nv_bfloat16 hy = __float2bfloat16_rn(aval.y);
        __nv_bfloat16 hz = __float2bfloat16_rn(aval.z);
        __nv_bfloat16 hw = __float2bfloat16_rn(aval.w);
        uint32_t hi01, hi23;
        { __nv_bfloat162 p; p.x = hx; p.y = hy; hi01 = *reinterpret_cast<uint32_t*>(&p); }
        { __nv_bfloat162 p; p.x = hz; p.y = hw; hi23 = *reinterpret_cast<uint32_t*>(&p); }
        uint32_t lo01 = pack2(aval.x - __bfloat162float(hx), aval.y - __bfloat162float(hy));
        uint32_t lo23 = pack2(aval.z - __bfloat162float(hz), aval.w - __bfloat162float(hw));
        *(uint2*)(stg + OFF_AHI + arow * 80 + akq * 8) = make_uint2(hi01, hi23);
        *(uint2*)(stg + OFF_ALO + arow * 80 + akq * 8) = make_uint2(lo01, lo23);
        *(uint4*)(stg + OFF_BHI + brow0 * 80 + bkq0 * 16) = bhv[0];
        *(uint4*)(stg + OFF_BHI + brow1 * 80 + bkq1 * 16) = bhv[1];
        *(uint4*)(stg + OFF_BLO + brow0 * 80 + bkq0 * 16) = blv[0];
        *(uint4*)(stg + OFF_BLO + brow1 * 80 + bkq1 * 16) = blv[1];
    };

    float acc[2][4][4];
#pragma unroll
    for (int i = 0; i < 2; i++)
#pragma unroll
        for (int j = 0; j < 4; j++)
#pragma unroll
            for (int c = 0; c < 4; c++) acc[i][j][c] = 0.f;

    prefetch(0);
    store_stage(0);
    __syncthreads();

#pragma unroll 1
    for (int c = 0; c < 24; ++c) {
        if (c < 23) prefetch(c + 1);
        const char* stg = smem + (c & 1) * ST_BYTES;
#pragma unroll
        for (int ks = 0; ks < 2; ++ks) {
            uint32_t ah[2][4], al[2][4], bh[4][2], bl[4][2];
            // A frag addresses: row = wm*32 + ms*16 + g(+8), k = ks*16 + 2t(+1,+8)
#pragma unroll
            for (int ms = 0; ms < 2; ++ms) {
                const char* base = stg + OFF_AHI + (wm * 32 + ms * 16 + g) * 80 + ks * 32 + t4 * 4;
                ah[ms][0] = *(const uint32_t*)(base);
                ah[ms][1] = *(const uint32_t*)(base + 8 * 80);
                ah[ms][2] = *(const uint32_t*)(base + 16);
                ah[ms][3] = *(const uint32_t*)(base + 8 * 80 + 16);
            }
#pragma unroll
            for (int ns = 0; ns < 4; ++ns) {
                const char* base = stg + OFF_BHI + (wn * 32 + ns * 8 + g) * 80 + ks * 32 + t4 * 4;
                bh[ns][0] = *(const uint32_t*)(base);
                bh[ns][1] = *(const uint32_t*)(base + 16);
            }
#pragma unroll
            for (int ms = 0; ms < 2; ++ms)
#pragma unroll
                for (int ns = 0; ns < 4; ++ns) hmma(acc[ms][ns], ah[ms], bh[ns]);
#pragma unroll
            for (int ns = 0; ns < 4; ++ns) {
                const char* base = stg + OFF_BLO + (wn * 32 + ns * 8 + g) * 80 + ks * 32 + t4 * 4;
                bl[ns][0] = *(const uint32_t*)(base);
                bl[ns][1] = *(const uint32_t*)(base + 16);
            }
#pragma unroll
            for (int ms = 0; ms < 2; ++ms)
#pragma unroll
                for (int ns = 0; ns < 4; ++ns) hmma(acc[ms][ns], ah[ms], bl[ns]);
#pragma unroll
            for (int ms = 0; ms < 2; ++ms) {
                const char* base = stg + OFF_ALO + (wm * 32 + ms * 16 + g) * 80 + ks * 32 + t4 * 4;
                al[ms][0] = *(const uint32_t*)(base);
                al[ms][1] = *(const uint32_t*)(base + 8 * 80);
                al[ms][2] = *(const uint32_t*)(base + 16);
                al[ms][3] = *(const uint32_t*)(base + 8 * 80 + 16);
            }
#pragma unroll
            for (int ms = 0; ms < 2; ++ms)
#pragma unroll
                for (int ns = 0; ns < 4; ++ns) hmma(acc[ms][ns], al[ms], bh[ns]);
        }
        if (c < 23) {
            __syncthreads();           // everyone done reading buf[(c+1)&1] (chunk c-1)
            store_stage((c + 1) & 1);
            __syncthreads();
        }
    }

    // ---------------- epilogue: bias + LayerNorm + ReLU (+ linear) ----------------
    float* partS = (float*)(smem + OFF_PART_S);   // [8][64]
    float* partQ = (float*)(smem + OFF_PART_Q);   // [8][64]
    float* meanA = (float*)(smem + OFF_MEAN);     // [64]
    float* rstdA = (float*)(smem + OFF_RSTD);     // [64]

    // per-thread column params (cols = wn*32 + ns*8 + 2t + {0,1})
    float2 bs[4], gm[4], bt[4], lwv[4];
#pragma unroll
    for (int ns = 0; ns < 4; ++ns) {
        int col = wn * 32 + ns * 8 + t4 * 2;
        bs[ns] = *(const float2*)(bias + col);
        gm[ns] = *(const float2*)(gam + col);
        bt[ns] = *(const float2*)(bet + col);
        if (DO_LIN) lwv[ns] = *(const float2*)(lw + col);
    }
    // add bias
#pragma unroll
    for (int ms = 0; ms < 2; ++ms)
#pragma unroll
        for (int ns = 0; ns < 4; ++ns) {
            acc[ms][ns][0] += bs[ns].x; acc[ms][ns][1] += bs[ns].y;
            acc[ms][ns][2] += bs[ns].x; acc[ms][ns][3] += bs[ns].y;
        }
    // row sums / sumsq (rows: wm*32 + ms*16 + h*8 + g)
#pragma unroll
    for (int ms = 0; ms < 2; ++ms) {
        float s0 = 0.f, q0 = 0.f, s1 = 0.f, q1 = 0.f;
#pragma unroll
        for (int ns = 0; ns < 4; ++ns) {
            s0 += acc[ms][ns][0] + acc[ms][ns][1];
            q0 += acc[ms][ns][0] * acc[ms][ns][0] + acc[ms][ns][1] * acc[ms][ns][1];
            s1 += acc[ms][ns][2] + acc[ms][ns][3];
            q1 += acc[ms][ns][2] * acc[ms][ns][2] + acc[ms][ns][3] * acc[ms][ns][3];
        }
#pragma unroll
        for (int o = 1; o <= 2; o <<= 1) {
            s0 += __shfl_xor_sync(0xffffffffu, s0, o);
            q0 += __shfl_xor_sync(0xffffffffu, q0, o);
            s1 += __shfl_xor_sync(0xffffffffu, s1, o);
            q1 += __shfl_xor_sync(0xffffffffu, q1, o);
        }
        if (t4 == 0) {
            int r0 = wm * 32 + ms * 16 + g;
            partS[wn * 64 + r0] = s0;      partQ[wn * 64 + r0] = q0;
            partS[wn * 64 + r0 + 8] = s1;  partQ[wn * 64 + r0 + 8] = q1;
        }
    }
    __syncthreads();
    if (tid < 64) {
        float s = 0.f, q = 0.f;
#pragma unroll
        for (int w = 0; w < 8; ++w) { s += partS[w * 64 + tid]; q += partQ[w * 64 + tid]; }
        float mean = s * (1.f / 256.f);
        float var = q * (1.f / 256.f) - mean * mean;
        meanA[tid] = mean;
        rstdA[tid] = rsqrtf(var + EPS);
    }
    __syncthreads();

    // normalize, relu; then store h1 or reduce dot for dpo
    float mu[2][2], rs[2][2];
#pragma unroll
    for (int ms = 0; ms < 2; ++ms)
#pragma unroll
        for (int h = 0; h < 2; ++h) {
            int lr = wm * 32 + ms * 16 + h * 8 + g;
            mu[ms][h] = meanA[lr];
            rs[ms][h] = rstdA[lr];
        }
    float y[2][4][4];
#pragma unroll
    for (int ms = 0; ms < 2; ++ms)
#pragma unroll
        for (int ns = 0; ns < 4; ++ns) {
            y[ms][ns][0] = fmaxf((acc[ms][ns][0] - mu[ms][0]) * rs[ms][0] * gm[ns].x + bt[ns].x, 0.f);
            y[ms][ns][1] = fmaxf((acc[ms][ns][1] - mu[ms][0]) * rs[ms][0] * gm[ns].y + bt[ns].y, 0.f);
            y[ms][ns][2] = fmaxf((acc[ms][ns][2] - mu[ms][1]) * rs[ms][1] * gm[ns].x + bt[ns].x, 0.f);
            y[ms][ns][3] = fmaxf((acc[ms][ns][3] - mu[ms][1]) * rs[ms][1] * gm[ns].y + bt[ns].y, 0.f);
        }

    if (!DO_LIN) {
#pragma unroll
        for (int ms = 0; ms < 2; ++ms)
#pragma unroll
            for (int h = 0; h < 2; ++h) {
                int grow = bm + wm * 32 + ms * 16 + h * 8 + g;
#pragma unroll
                for (int ns = 0; ns < 4; ++ns) {
                    int col = wn * 32 + ns * 8 + t4 * 2;
                    *(float2*)(out + (size_t)grow * FF + col) =
                        make_float2(y[ms][ns][h * 2], y[ms][ns][h * 2 + 1]);
                }
            }
    } else {
        __syncthreads();   // stats phase fully done before partS reuse
#pragma unroll
        for (int ms = 0; ms < 2; ++ms) {
            float p0 = 0.f, p1 = 0.f;
#pragma unroll
            for (int ns = 0; ns < 4; ++ns) {
                p0 += y[ms][ns][0] * lwv[ns].x + y[ms][ns][1] * lwv[ns].y;
                p1 += y[ms][ns][2] * lwv[ns].x + y[ms][ns][3] * lwv[ns].y;
            }
#pragma unroll
            for (int o = 1; o <= 2; o <<= 1) {
                p0 += __shfl_xor_sync(0xffffffffu, p0, o);
                p1 += __shfl_xor_sync(0xffffffffu, p1, o);
            }
            if (t4 == 0) {
                int r0 = wm * 32 + ms * 16 + g;
                partS[wn * 64 + r0] = p0;
                partS[wn * 64 + r0 + 8] = p1;
            }
        }
        __syncthreads();
        if (tid < 64) {
            float s = 0.f;
#pragma unroll
            for (int w = 0; w < 8; ++w) s += partS[w * 64 + tid];
            out[bm + tid] = fmaxf(s + lb[0], 0.f);
        }
    }
}

// ---------------- per-n inclusive cumsum of target ----------------
__global__ void cumsum_kernel(const int* __restrict__ target) {
    int n = blockIdx.x, t = threadIdx.x;   // 512 threads
    __shared__ int s[LL];
    s[t] = target[n * LL + t];
    __syncthreads();
#pragma unroll
    for (int off = 1; off < LL; off <<= 1) {
        int v = (t >= off) ? s[t - off] : 0;
        __syncthreads();
        s[t] += v;
        __syncthreads();
    }
    g_cum[n * LL + t] = s[t];
}

// ---------------- length regulation: gather + zero-fill ----------------
__global__ void length_reg_kernel(const float* __restrict__ x,
                                  float* __restrict__ out) {
    unsigned tidg = blockIdx.x * 256u + threadIdx.x;  // over 16*4096*64 float4
    int c4 = tidg & 63;
    int t = (tidg >> 6) & 4095;
    int n = tidg >> 18;
    const int* cn = g_cum + n * LL;
    int total = __ldg(cn + LL - 1);
    float4 v = make_float4(0.f, 0.f, 0.f, 0.f);
    if (t < total) {
        int lo = 0, hi = LL;
        while (lo < hi) {
            int mid = (lo + hi) >> 1;
            if (__ldg(cn + mid) > t) hi = mid; else lo = mid + 1;
        }
        v = *(const float4*)(x + ((n << 9) + lo) * DD + c4 * 4);
    }
    *(float4*)(out + (size_t)tidg * 4) = v;
}

// ---------------- launch ----------------
extern "C" void kernel_launch(void* const* d_in, const int* in_sizes, int n_in,
                              void* d_out, int out_size) {
    const float* x   = (const float*)d_in[0];
    const float* c1w = (const float*)d_in[1];
    const float* c1b = (const float*)d_in[2];
    const float* g1  = (const float*)d_in[3];
    const float* b1  = (const float*)d_in[4];
    const float* c2w = (const float*)d_in[5];
    const float* c2b = (const float*)d_in[6];
    const float* g2  = (const float*)d_in[7];
    const float* b2  = (const float*)d_in[8];
    const float* lw  = (const float*)d_in[9];
    const float* lb  = (const float*)d_in[10];
    const int*   tgt = (const int*)d_in[11];

    float* out = (float*)d_out;                         // [16,4096,256]
    float* dpo = out + (size_t)NB * TT * DD;            // [16,512]

    float* h1;
    __nv_bfloat16 *b1hi, *b1lo, *b2hi, *b2lo;
    cudaGetSymbolAddress((void**)&h1, g_h1);
    cudaGetSymbolAddress((void**)&b1hi, g_b1hi);
    cudaGetSymbolAddress((void**)&b1lo, g_b1lo);
    cudaGetSymbolAddress((void**)&b2hi, g_b2hi);
    cudaGetSymbolAddress((void**)&b2lo, g_b2lo);

    cudaFuncSetAttribute(conv_fused_kernel<false>,
                         cudaFuncAttributeMaxDynamicSharedMemorySize, SMEM_CONV);
    cudaFuncSetAttribute(conv_fused_kernel<true>,
                         cudaFuncAttributeMaxDynamicSharedMemorySize, SMEM_CONV);

    // duration predictor chain (HMMA tensor GEMMs, fused LN/ReLU/linear)
    prep_b_kernel<<<768, 256>>>(c1w, c2w);
    conv_fused_kernel<false><<<128, 512, SMEM_CONV>>>(x, b1hi, b1lo, c1b, g1, b1,
                                                      nullptr, nullptr, h1);
    conv_fused_kernel<true><<<128, 512, SMEM_CONV>>>(h1, b2hi, b2lo, c2b, g2, b2,
                                                     lw, lb, dpo);
    // length regulation chain
    cumsum_kernel<<<NB, LL>>>(tgt);
    length_reg_kernel<<<(NB * TT * (DD / 4)) / 256, 256>>>(x, out);
}

// round 6
// speedup vs baseline: 1.9791x; 1.0196x over previous
#include <cuda_runtime.h>
#include <cuda_bf16.h>
#include <cstdint>
#include <math.h>

// Problem constants
#define NB   16
#define LL   512
#define DD   256
#define FF   256
#define TT   4096
#define MM   (NB * LL)        // 8192 rows
#define KTOT 768              // D * 3
#define EPS  1e-5f

// ---------------- scratch (static device globals; no allocs) ----------------
__device__ __align__(16) float g_h1[MM * FF];
__device__ __align__(16) __nv_bfloat16 g_b1hi[FF * KTOT];
__device__ __align__(16) __nv_bfloat16 g_b1lo[FF * KTOT];
__device__ __align__(16) __nv_bfloat16 g_b2hi[FF * KTOT];
__device__ __align__(16) __nv_bfloat16 g_b2lo[FF * KTOT];
__device__ int   g_cum[NB * LL];

// ============ fused weight prep (blocks 0..767) + cumsum (block 768) ========
__global__ void prep_b_cumsum_kernel(const float* __restrict__ w1,
                                     const float* __restrict__ w2,
                                     const int* __restrict__ target) {
    if (blockIdx.x == 768) {
        int wid = threadIdx.x >> 5, lane = threadIdx.x & 31;
#pragma unroll
        for (int r = 0; r < 2; ++r) {
            int n = wid * 2 + r;
            const int* src = target + n * LL + lane * 16;
            int v[16];
#pragma unroll
            for (int j = 0; j < 4; ++j)
                *(int4*)(v + j * 4) = *(const int4*)(src + j * 4);
#pragma unroll
            for (int j = 1; j < 16; ++j) v[j] += v[j - 1];
            int total = v[15];
            int pre = total;
#pragma unroll
            for (int o = 1; o < 32; o <<= 1) {
                int t = __shfl_up_sync(0xffffffffu, pre, o);
                if (lane >= o) pre += t;
            }
            pre -= total;   // exclusive prefix
#pragma unroll
            for (int j = 0; j < 16; ++j) v[j] += pre;
            int* dst = g_cum + n * LL + lane * 16;
#pragma unroll
            for (int j = 0; j < 4; ++j)
                *(int4*)(dst + j * 4) = *(const int4*)(v + j * 4);
        }
        return;
    }
    int i = blockIdx.x * 256 + threadIdx.x;     // over 256*768
    int f = i / KTOT;
    int kf = i - f * KTOT;
    int k = kf >> 8;
    int d = kf & 255;
    float v1 = w1[f * KTOT + d * 3 + k];
    float v2 = w2[f * KTOT + d * 3 + k];
    __nv_bfloat16 h1 = __float2bfloat16_rn(v1);
    __nv_bfloat16 h2 = __float2bfloat16_rn(v2);
    g_b1hi[i] = h1;
    g_b1lo[i] = __float2bfloat16_rn(v1 - __bfloat162float(h1));
    g_b2hi[i] = h2;
    g_b2lo[i] = __float2bfloat16_rn(v2 - __bfloat162float(h2));
}

// ============== fused conv(K=3) GEMM + LayerNorm + ReLU (+ linear) ==========
// Per CTA: 64 rows x 256 cols. 512 threads = 16 warps (2m x 8n), warp tile 32x32.
// K loop: 24 chunks of 32 (3 taps x 8 d-chunks), bf16 hi/lo 3-pass HMMA.
// Single __syncthreads per chunk: top-of-iter barrier both publishes buf[c&1]
// (stored last iter) and licenses overwrite of buf[(c+1)&1] (read 2 iters ago).

#define ST_BYTES   51200            // one stage: Ahi|Alo|Bhi|Blo (80B rows)
#define OFF_AHI    0                // 64 rows x 80B
#define OFF_ALO    5120
#define OFF_BHI    10240            // 256 rows x 80B
#define OFF_BLO    30720
#define OFF_PART_S (2 * ST_BYTES)           // 8 x 64 floats
#define OFF_PART_Q (OFF_PART_S + 2048)
#define OFF_MEAN   (OFF_PART_Q + 2048)      // 64 floats
#define OFF_RSTD   (OFF_MEAN + 256)
#define SMEM_CONV  (OFF_RSTD + 256)

__device__ __forceinline__ void hmma(float* d, const uint32_t* a, const uint32_t* b) {
    asm volatile(
        "mma.sync.aligned.m16n8k16.row.col.f32.bf16.bf16.f32 "
        "{%0,%1,%2,%3}, {%4,%5,%6,%7}, {%8,%9}, {%0,%1,%2,%3};"
        : "+f"(d[0]), "+f"(d[1]), "+f"(d[2]), "+f"(d[3])
        : "r"(a[0]), "r"(a[1]), "r"(a[2]), "r"(a[3]), "r"(b[0]), "r"(b[1]));
}

__device__ __forceinline__ uint32_t pack2(float a, float b) {
    __nv_bfloat162 t = __floats2bfloat162_rn(a, b);
    return *reinterpret_cast<uint32_t*>(&t);
}

template <bool DO_LIN>
__global__ __launch_bounds__(512, 1)
void conv_fused_kernel(const float* __restrict__ A,
                       const __nv_bfloat16* __restrict__ Bhi,
                       const __nv_bfloat16* __restrict__ Blo,
                       const float* __restrict__ bias,
                       const float* __restrict__ gam,
                       const float* __restrict__ bet,
                       const float* __restrict__ lw,
                       const float* __restrict__ lb,
                       float* __restrict__ out)   // h1 if !DO_LIN, dpo if DO_LIN
{
    extern __shared__ char smem[];
    const int tid = threadIdx.x;
    const int wid = tid >> 5;
    const int lane = tid & 31;
    const int g = lane >> 2;          // groupID
    const int t4 = lane & 3;          // thread-in-group
    const int wm = wid >> 3;          // 0..1
    const int wn = wid & 7;           // 0..7
    const int bm = blockIdx.x * 64;
    const int n = bm >> 9;
    const int l0 = bm & 511;

    // prefetch register sets (identical footprint to R3's proven compile)
    float4 aval;
    uint4  bhv[2], blv[2];
    const int arow = tid >> 3;        // A: row 0..63
    const int akq = tid & 7;          // float4 along d (32 floats = 8 float4)
    const int brow0 = tid >> 2, bkq0 = tid & 3;          // B slot 1
    const int brow1 = (tid + 512) >> 2, bkq1 = tid & 3;  // B slot 2

    auto prefetch = [&](int c) {
        const int tap = c >> 3;
        const int dc = (c & 7) * 32;
        int lsrc = l0 + arow + tap - 1;
        aval = make_float4(0.f, 0.f, 0.f, 0.f);
        if (lsrc >= 0 && lsrc < LL)
            aval = *(const float4*)(A + (size_t)((n << 9) + lsrc) * DD + dc + akq * 4);
        const int kfb = tap * 256 + dc;
        bhv[0] = *(const uint4*)(Bhi + (size_t)brow0 * KTOT + kfb + bkq0 * 8);
        bhv[1] = *(const uint4*)(Bhi + (size_t)brow1 * KTOT + kfb + bkq1 * 8);
        blv[0] = *(const uint4*)(Blo + (size_t)brow0 * KTOT + kfb + bkq0 * 8);
        blv[1] = *(const uint4*)(Blo + (size_t)brow1 * KTOT + kfb + bkq1 * 8);
    };

    auto store_stage = [&](int s) {
        char* stg = smem + s * ST_BYTES;
        __nv_bfloat16 hx = __float2bfloat16_rn(aval.x);
        __nv_bfloat16 hy = __float2bfloat16_rn(aval.y);
        __nv_bfloat16 hz = __float2bfloat16_rn(aval.z);
        __nv_bfloat16 hw = __float2bfloat16_rn(aval.w);
        uint32_t hi01, hi23;
        { __nv_bfloat162 p; p.x = hx; p.y = hy; hi01 = *reinterpret_cast<uint32_t*>(&p); }
        { __nv_bfloat162 p; p.x = hz; p.y = hw; hi23 = *reinterpret_cast<uint32_t*>(&p); }
        uint32_t lo01 = pack2(aval.x - __bfloat162float(hx), aval.y - __bfloat162float(hy));
        uint32_t lo23 = pack2(aval.z - __bfloat162float(hz), aval.w - __bfloat162float(hw));
        *(uint2*)(stg + OFF_AHI + arow * 80 + akq * 8) = make_uint2(hi01, hi23);
        *(uint2*)(stg + OFF_ALO + arow * 80 + akq * 8) = make_uint2(lo01, lo23);
        *(uint4*)(stg + OFF_BHI + brow0 * 80 + bkq0 * 16) = bhv[0];
        *(uint4*)(stg + OFF_BHI + brow1 * 80 + bkq1 * 16) = bhv[1];
        *(uint4*)(stg + OFF_BLO + brow0 * 80 + bkq0 * 16) = blv[0];
        *(uint4*)(stg + OFF_BLO + brow1 * 80 + bkq1 * 16) = blv[1];
    };

    float acc[2][4][4];
#pragma unroll
    for (int i = 0; i < 2; i++)
#pragma unroll
        for (int j = 0; j < 4; j++)
#pragma unroll
            for (int c = 0; c < 4; c++) acc[i][j][c] = 0.f;

    // prologue: stage 0 stored, regs hold chunk 1
    prefetch(0);
    store_stage(0);
    prefetch(1);

#pragma unroll 1
    for (int c = 0; c < 24; ++c) {
        __syncthreads();   // buf c&1 published; buf (c+1)&1 free for overwrite
        if (c < 23) store_stage((c + 1) & 1);   // from regs prefetched at c-1
        if (c < 22) prefetch(c + 2);            // LDGs overlap compute(c)
        const char* stg = smem + (c & 1) * ST_BYTES;
#pragma unroll
        for (int ks = 0; ks < 2; ++ks) {
            uint32_t ah[2][4], al[2][4], bh[4][2], bl[4][2];
#pragma unroll
            for (int ms = 0; ms < 2; ++ms) {
                const char* base = stg + OFF_AHI + (wm * 32 + ms * 16 + g) * 80 + ks * 32 + t4 * 4;
                ah[ms][0] = *(const uint32_t*)(base);
                ah[ms][1] = *(const uint32_t*)(base + 8 * 80);
                ah[ms][2] = *(const uint32_t*)(base + 16);
                ah[ms][3] = *(const uint32_t*)(base + 8 * 80 + 16);
            }
#pragma unroll
            for (int ns = 0; ns < 4; ++ns) {
                const char* base = stg + OFF_BHI + (wn * 32 + ns * 8 + g) * 80 + ks * 32 + t4 * 4;
                bh[ns][0] = *(const uint32_t*)(base);
                bh[ns][1] = *(const uint32_t*)(base + 16);
            }
#pragma unroll
            for (int ms = 0; ms < 2; ++ms)
#pragma unroll
                for (int ns = 0; ns < 4; ++ns) hmma(acc[ms][ns], ah[ms], bh[ns]);
#pragma unroll
            for (int ns = 0; ns < 4; ++ns) {
                const char* base = stg + OFF_BLO + (wn * 32 + ns * 8 + g) * 80 + ks * 32 + t4 * 4;
                bl[ns][0] = *(const uint32_t*)(base);
                bl[ns][1] = *(const uint32_t*)(base + 16);
            }
#pragma unroll
            for (int ms = 0; ms < 2; ++ms)
#pragma unroll
                for (int ns = 0; ns < 4; ++ns) hmma(acc[ms][ns], ah[ms], bl[ns]);
#pragma unroll
            for (int ms = 0; ms < 2; ++ms) {
                const char* base = stg + OFF_ALO + (wm * 32 + ms * 16 + g) * 80 + ks * 32 + t4 * 4;
                al[ms][0] = *(const uint32_t*)(base);
                al[ms][1] = *(const uint32_t*)(base + 8 * 80);
                al[ms][2] = *(const uint32_t*)(base + 16);
                al[ms][3] = *(const uint32_t*)(base + 8 * 80 + 16);
            }
#pragma unroll
            for (int ms = 0; ms < 2; ++ms)
#pragma unroll
                for (int ns = 0; ns < 4; ++ns) hmma(acc[ms][ns], al[ms], bh[ns]);
        }
    }

    // ---------------- epilogue: bias + LayerNorm + ReLU (+ linear) ----------------
    float* partS = (float*)(smem + OFF_PART_S);   // [8][64]
    float* partQ = (float*)(smem + OFF_PART_Q);   // [8][64]
    float* meanA = (float*)(smem + OFF_MEAN);     // [64]
    float* rstdA = (float*)(smem + OFF_RSTD);     // [64]

    float2 bs[4], gm[4], bt[4], lwv[4];
#pragma unroll
    for (int ns = 0; ns < 4; ++ns) {
        int col = wn * 32 + ns * 8 + t4 * 2;
        bs[ns] = *(const float2*)(bias + col);
        gm[ns] = *(const float2*)(gam + col);
        bt[ns] = *(const float2*)(bet + col);
        if (DO_LIN) lwv[ns] = *(const float2*)(lw + col);
    }
#pragma unroll
    for (int ms = 0; ms < 2; ++ms)
#pragma unroll
        for (int ns = 0; ns < 4; ++ns) {
            acc[ms][ns][0] += bs[ns].x; acc[ms][ns][1] += bs[ns].y;
            acc[ms][ns][2] += bs[ns].x; acc[ms][ns][3] += bs[ns].y;
        }
    __syncthreads();   // mainloop smem reads done before stats-area writes
#pragma unroll
    for (int ms = 0; ms < 2; ++ms) {
        float s0 = 0.f, q0 = 0.f, s1 = 0.f, q1 = 0.f;
#pragma unroll
        for (int ns = 0; ns < 4; ++ns) {
            s0 += acc[ms][ns][0] + acc[ms][ns][1];
            q0 += acc[ms][ns][0] * acc[ms][ns][0] + acc[ms][ns][1] * acc[ms][ns][1];
            s1 += acc[ms][ns][2] + acc[ms][ns][3];
            q1 += acc[ms][ns][2] * acc[ms][ns][2] + acc[ms][ns][3] * acc[ms][ns][3];
        }
#pragma unroll
        for (int o = 1; o <= 2; o <<= 1) {
            s0 += __shfl_xor_sync(0xffffffffu, s0, o);
            q0 += __shfl_xor_sync(0xffffffffu, q0, o);
            s1 += __shfl_xor_sync(0xffffffffu, s1, o);
            q1 += __shfl_xor_sync(0xffffffffu, q1, o);
        }
        if (t4 == 0) {
            int r0 = wm * 32 + ms * 16 + g;
            partS[wn * 64 + r0] = s0;      partQ[wn * 64 + r0] = q0;
            partS[wn * 64 + r0 + 8] = s1;  partQ[wn * 64 + r0 + 8] = q1;
        }
    }
    __syncthreads();
    if (tid < 64) {
        float s = 0.f, q = 0.f;
#pragma unroll
        for (int w = 0; w < 8; ++w) { s += partS[w * 64 + tid]; q += partQ[w * 64 + tid]; }
        float mean = s * (1.f / 256.f);
        float var = q * (1.f / 256.f) - mean * mean;
        meanA[tid] = mean;
        rstdA[tid] = rsqrtf(var + EPS);
    }
    __syncthreads();

    float mu[2][2], rs[2][2];
#pragma unroll
    for (int ms = 0; ms < 2; ++ms)
#pragma unroll
        for (int h = 0; h < 2; ++h) {
            int lr = wm * 32 + ms * 16 + h * 8 + g;
            mu[ms][h] = meanA[lr];
            rs[ms][h] = rstdA[lr];
        }
    float y[2][4][4];
#pragma unroll
    for (int ms = 0; ms < 2; ++ms)
#pragma unroll
        for (int ns = 0; ns < 4; ++ns) {
            y[ms][ns][0] = fmaxf((acc[ms][ns][0] - mu[ms][0]) * rs[ms][0] * gm[ns].x + bt[ns].x, 0.f);
            y[ms][ns][1] = fmaxf((acc[ms][ns][1] - mu[ms][0]) * rs[ms][0] * gm[ns].y + bt[ns].y, 0.f);
            y[ms][ns][2] = fmaxf((acc[ms][ns][2] - mu[ms][1]) * rs[ms][1] * gm[ns].x + bt[ns].x, 0.f);
            y[ms][ns][3] = fmaxf((acc[ms][ns][3] - mu[ms][1]) * rs[ms][1] * gm[ns].y + bt[ns].y, 0.f);
        }

    if (!DO_LIN) {
#pragma unroll
        for (int ms = 0; ms < 2; ++ms)
#pragma unroll
            for (int h = 0; h < 2; ++h) {
                int grow = bm + wm * 32 + ms * 16 + h * 8 + g;
#pragma unroll
                for (int ns = 0; ns < 4; ++ns) {
                    int col = wn * 32 + ns * 8 + t4 * 2;
                    *(float2*)(out + (size_t)grow * FF + col) =
                        make_float2(y[ms][ns][h * 2], y[ms][ns][h * 2 + 1]);
                }
            }
    } else {
        __syncthreads();   // stats phase fully done before partS reuse
#pragma unroll
        for (int ms = 0; ms < 2; ++ms) {
            float p0 = 0.f, p1 = 0.f;
#pragma unroll
            for (int ns = 0; ns < 4; ++ns) {
                p0 += y[ms][ns][0] * lwv[ns].x + y[ms][ns][1] * lwv[ns].y;
                p1 += y[ms][ns][2] * lwv[ns].x + y[ms][ns][3] * lwv[ns].y;
            }
#pragma unroll
            for (int o = 1; o <= 2; o <<= 1) {
                p0 += __shfl_xor_sync(0xffffffffu, p0, o);
                p1 += __shfl_xor_sync(0xffffffffu, p1, o);
            }
            if (t4 == 0) {
                int r0 = wm * 32 + ms * 16 + g;
                partS[wn * 64 + r0] = p0;
                partS[wn * 64 + r0 + 8] = p1;
            }
        }
        __syncthreads();
        if (tid < 64) {
            float s = 0.f;
#pragma unroll
            for (int w = 0; w < 8; ++w) s += partS[w * 64 + tid];
            out[bm + tid] = fmaxf(s + lb[0], 0.f);
        }
    }
}

// ---------------- length regulation: gather + zero-fill ----------------
__global__ void length_reg_kernel(const float* __restrict__ x,
                                  float* __restrict__ out) {
    unsigned tidg = blockIdx.x * 256u + threadIdx.x;  // over 16*4096*64 float4
    int c4 = tidg & 63;
    int t = (tidg >> 6) & 4095;
    int n = tidg >> 18;
    const int* cn = g_cum + n * LL;
    int total = __ldg(cn + LL - 1);
    float4 v = make_float4(0.f, 0.f, 0.f, 0.f);
    if (t < total) {
        int lo = 0, hi = LL;
        while (lo < hi) {
            int mid = (lo + hi) >> 1;
            if (__ldg(cn + mid) > t) hi = mid; else lo = mid + 1;
        }
        v = *(const float4*)(x + ((n << 9) + lo) * DD + c4 * 4);
    }
    __stcs((float4*)(out + (size_t)tidg * 4), v);
}

// ---------------- launch ----------------
extern "C" void kernel_launch(void* const* d_in, const int* in_sizes, int n_in,
                              void* d_out, int out_size) {
    const float* x   = (const float*)d_in[0];
    const float* c1w = (const float*)d_in[1];
    const float* c1b = (const float*)d_in[2];
    const float* g1  = (const float*)d_in[3];
    const float* b1  = (const float*)d_in[4];
    const float* c2w = (const float*)d_in[5];
    const float* c2b = (const float*)d_in[6];
    const float* g2  = (const float*)d_in[7];
    const float* b2  = (const float*)d_in[8];
    const float* lw  = (const float*)d_in[9];
    const float* lb  = (const float*)d_in[10];
    const int*   tgt = (const int*)d_in[11];

    float* out = (float*)d_out;                         // [16,4096,256]
    float* dpo = out + (size_t)NB * TT * DD;            // [16,512]

    float* h1;
    __nv_bfloat16 *b1hi, *b1lo, *b2hi, *b2lo;
    cudaGetSymbolAddress((void**)&h1, g_h1);
    cudaGetSymbolAddress((void**)&b1hi, g_b1hi);
    cudaGetSymbolAddress((void**)&b1lo, g_b1lo);
    cudaGetSymbolAddress((void**)&b2hi, g_b2hi);
    cudaGetSymbolAddress((void**)&b2lo, g_b2lo);

    cudaFuncSetAttribute(conv_fused_kernel<false>,
                         cudaFuncAttributeMaxDynamicSharedMemorySize, SMEM_CONV);
    cudaFuncSetAttribute(conv_fused_kernel<true>,
                         cudaFuncAttributeMaxDynamicSharedMemorySize, SMEM_CONV);

    prep_b_cumsum_kernel<<<769, 256>>>(c1w, c2w, tgt);
    conv_fused_kernel<false><<<128, 512, SMEM_CONV>>>(x, b1hi, b1lo, c1b, g1, b1,
                                                      nullptr, nullptr, h1);
    conv_fused_kernel<true><<<128, 512, SMEM_CONV>>>(h1, b2hi, b2lo, c2b, g2, b2,
                                                     lw, lb, dpo);
    length_reg_kernel<<<(NB * TT * (DD / 4)) / 256, 256>>>(x, out);
}

// round 7
// speedup vs baseline: 1.9973x; 1.0092x over previous
#include <cuda_runtime.h>
#include <cuda_bf16.h>
#include <cstdint>
#include <math.h>

// Problem constants
#define NB   16
#define LL   512
#define DD   256
#define FF   256
#define TT   4096
#define MM   (NB * LL)        // 8192 rows
#define KTOT 768              // D * 3
#define EPS  1e-5f

// ---------------- scratch (static device globals; no allocs) ----------------
__device__ __align__(16) float g_h1[MM * FF];
__device__ __align__(16) __nv_bfloat16 g_b1hi[FF * KTOT];
__device__ __align__(16) __nv_bfloat16 g_b1lo[FF * KTOT];
__device__ __align__(16) __nv_bfloat16 g_b2hi[FF * KTOT];
__device__ __align__(16) __nv_bfloat16 g_b2lo[FF * KTOT];
__device__ int   g_idx[NB * TT];    // length-regulation gather index (-1 = pad)

// ==== fused weight prep (blocks 0..767) + cumsum->index scatter (block 768) ==
__global__ void prep_b_cumsum_kernel(const float* __restrict__ w1,
                                     const float* __restrict__ w2,
                                     const int* __restrict__ target) {
    if (blockIdx.x == 768) {
        // 256 threads = 8 warps; warp w handles sequences 2w, 2w+1
        int wid = threadIdx.x >> 5, lane = threadIdx.x & 31;
#pragma unroll
        for (int r = 0; r < 2; ++r) {
            int n = wid * 2 + r;
            const int* src = target + n * LL + lane * 16;
            int v[16];
#pragma unroll
            for (int j = 0; j < 4; ++j)
                *(int4*)(v + j * 4) = *(const int4*)(src + j * 4);
#pragma unroll
            for (int j = 1; j < 16; ++j) v[j] += v[j - 1];
            int total = v[15];
            int pre = total;
#pragma unroll
            for (int o = 1; o < 32; o <<= 1) {
                int t = __shfl_up_sync(0xffffffffu, pre, o);
                if (lane >= o) pre += t;
            }
            pre -= total;   // exclusive prefix before this lane's chunk
#pragma unroll
            for (int j = 0; j < 16; ++j) v[j] += pre;   // global inclusive
            // scatter: element l=lane*16+j covers t in [start, v[j])
            int* idxn = g_idx + n * TT;
            int start = pre;
#pragma unroll
            for (int j = 0; j < 16; ++j) {
                int l = lane * 16 + j;
                for (int t = start; t < v[j]; ++t) idxn[t] = l;
                start = v[j];
            }
            int tot = __shfl_sync(0xffffffffu, v[15], 31);
            for (int t = tot + lane; t < TT; t += 32) idxn[t] = -1;
        }
        return;
    }
    int i = blockIdx.x * 256 + threadIdx.x;     // over 256*768
    int f = i / KTOT;
    int kf = i - f * KTOT;
    int k = kf >> 8;
    int d = kf & 255;
    float v1 = w1[f * KTOT + d * 3 + k];
    float v2 = w2[f * KTOT + d * 3 + k];
    __nv_bfloat16 h1 = __float2bfloat16_rn(v1);
    __nv_bfloat16 h2 = __float2bfloat16_rn(v2);
    g_b1hi[i] = h1;
    g_b1lo[i] = __float2bfloat16_rn(v1 - __bfloat162float(h1));
    g_b2hi[i] = h2;
    g_b2lo[i] = __float2bfloat16_rn(v2 - __bfloat162float(h2));
}

// ============== fused conv(K=3) GEMM + LayerNorm + ReLU (+ linear) ==========
// Per CTA: 64 rows x 256 cols. 512 threads = 16 warps (2m x 8n), warp tile 32x32.
// K loop: 24 chunks of 32, bf16 hi/lo 3-pass HMMA, fragments via ldmatrix.x4.

#define ST_BYTES   51200            // one stage: Ahi|Alo|Bhi|Blo (80B rows)
#define OFF_AHI    0                // 64 rows x 80B
#define OFF_ALO    5120
#define OFF_BHI    10240            // 256 rows x 80B
#define OFF_BLO    30720
#define OFF_PART_S (2 * ST_BYTES)           // 8 x 64 floats
#define OFF_PART_Q (OFF_PART_S + 2048)
#define OFF_MEAN   (OFF_PART_Q + 2048)      // 64 floats
#define OFF_RSTD   (OFF_MEAN + 256)
#define SMEM_CONV  (OFF_RSTD + 256)

__device__ __forceinline__ uint32_t smem_u32(const void* p) {
    uint32_t a;
    asm("{ .reg .u64 t; cvta.to.shared.u64 t, %1; cvt.u32.u64 %0, t; }"
        : "=r"(a) : "l"(p));
    return a;
}
__device__ __forceinline__ void ldsm4(uint32_t& r0, uint32_t& r1,
                                      uint32_t& r2, uint32_t& r3, uint32_t addr) {
    asm volatile("ldmatrix.sync.aligned.m8n8.x4.shared.b16 {%0,%1,%2,%3}, [%4];"
                 : "=r"(r0), "=r"(r1), "=r"(r2), "=r"(r3) : "r"(addr));
}
__device__ __forceinline__ void hmma(float* d, const uint32_t* a, const uint32_t* b) {
    asm volatile(
        "mma.sync.aligned.m16n8k16.row.col.f32.bf16.bf16.f32 "
        "{%0,%1,%2,%3}, {%4,%5,%6,%7}, {%8,%9}, {%0,%1,%2,%3};"
        : "+f"(d[0]), "+f"(d[1]), "+f"(d[2]), "+f"(d[3])
        : "r"(a[0]), "r"(a[1]), "r"(a[2]), "r"(a[3]), "r"(b[0]), "r"(b[1]));
}
__device__ __forceinline__ uint32_t pack2(float a, float b) {
    __nv_bfloat162 t = __floats2bfloat162_rn(a, b);
    return *reinterpret_cast<uint32_t*>(&t);
}

template <bool DO_LIN>
__global__ __launch_bounds__(512, 1)
void conv_fused_kernel(const float* __restrict__ A,
                       const __nv_bfloat16* __restrict__ Bhi,
                       const __nv_bfloat16* __restrict__ Blo,
                       const float* __restrict__ bias,
                       const float* __restrict__ gam,
                       const float* __restrict__ bet,
                       const float* __restrict__ lw,
                       const float* __restrict__ lb,
                       float* __restrict__ out)   // h1 if !DO_LIN, dpo if DO_LIN
{
    extern __shared__ char smem[];
    const uint32_t sbase = smem_u32(smem);
    const int tid = threadIdx.x;
    const int wid = tid >> 5;
    const int lane = tid & 31;
    const int g = lane >> 2;          // groupID
    const int t4 = lane & 3;          // thread-in-group
    const int wm = wid >> 3;          // 0..1
    const int wn = wid & 7;           // 0..7
    const int bm = blockIdx.x * 64;
    const int n = bm >> 9;
    const int l0 = bm & 511;

    // ldmatrix per-lane offsets: quad 0..3 -> (row_in_16, col_16B)
    const int quad = lane >> 3;
    const int lrow = (quad & 1) * 8 + (lane & 7);
    const int lcol = (quad >> 1) * 16;

    // prefetch register sets
    float4 aval;
    uint4  bhv[2], blv[2];
    const int arow = tid >> 3;        // A: row 0..63
    const int akq = tid & 7;          // float4 along d
    const int brow0 = tid >> 2, bkq0 = tid & 3;
    const int brow1 = (tid + 512) >> 2, bkq1 = tid & 3;

    auto prefetch = [&](int c) {
        const int tap = c >> 3;
        const int dc = (c & 7) * 32;
        int lsrc = l0 + arow + tap - 1;
        aval = make_float4(0.f, 0.f, 0.f, 0.f);
        if (lsrc >= 0 && lsrc < LL)
            aval = *(const float4*)(A + (size_t)((n << 9) + lsrc) * DD + dc + akq * 4);
        const int kfb = tap * 256 + dc;
        bhv[0] = *(const uint4*)(Bhi + (size_t)brow0 * KTOT + kfb + bkq0 * 8);
        bhv[1] = *(const uint4*)(Bhi + (size_t)brow1 * KTOT + kfb + bkq1 * 8);
        blv[0] = *(const uint4*)(Blo + (size_t)brow0 * KTOT + kfb + bkq0 * 8);
        blv[1] = *(const uint4*)(Blo + (size_t)brow1 * KTOT + kfb + bkq1 * 8);
    };

    auto store_stage = [&](int s) {
        char* stg = smem + s * ST_BYTES;
        __nv_bfloat16 hx = __float2bfloat16_rn(aval.x);
        __nv_bfloat16 hy = __float2bfloat16_rn(aval.y);
        __nv_bfloat16 hz = __float2bfloat16_rn(aval.z);
        __nv_bfloat16 hw = __float2bfloat16_rn(aval.w);
        uint32_t hi01, hi23;
        { __nv_bfloat162 p; p.x = hx; p.y = hy; hi01 = *reinterpret_cast<uint32_t*>(&p); }
        { __nv_bfloat162 p; p.x = hz; p.y = hw; hi23 = *reinterpret_cast<uint32_t*>(&p); }
        uint32_t lo01 = pack2(aval.x - __bfloat162float(hx), aval.y - __bfloat162float(hy));
        uint32_t lo23 = pack2(aval.z - __bfloat162float(hz), aval.w - __bfloat162float(hw));
        *(uint2*)(stg + OFF_AHI + arow * 80 + akq * 8) = make_uint2(hi01, hi23);
        *(uint2*)(stg + OFF_ALO + arow * 80 + akq * 8) = make_uint2(lo01, lo23);
        *(uint4*)(stg + OFF_BHI + brow0 * 80 + bkq0 * 16) = bhv[0];
        *(uint4*)(stg + OFF_BHI + brow1 * 80 + bkq1 * 16) = bhv[1];
        *(uint4*)(stg + OFF_BLO + brow0 * 80 + bkq0 * 16) = blv[0];
        *(uint4*)(stg + OFF_BLO + brow1 * 80 + bkq1 * 16) = blv[1];
    };

    float acc[2][4][4];
#pragma unroll
    for (int i = 0; i < 2; i++)
#pragma unroll
        for (int j = 0; j < 4; j++)
#pragma unroll
            for (int c = 0; c < 4; c++) acc[i][j][c] = 0.f;

    // prologue: stage 0 stored, regs hold chunk 1
    prefetch(0);
    store_stage(0);
    prefetch(1);

#pragma unroll 1
    for (int c = 0; c < 24; ++c) {
        __syncthreads();   // buf c&1 published; buf (c+1)&1 free for overwrite
        if (c < 23) store_stage((c + 1) & 1);
        if (c < 22) prefetch(c + 2);
        const uint32_t stg = sbase + (c & 1) * ST_BYTES;
#pragma unroll
        for (int ks = 0; ks < 2; ++ks) {
            uint32_t ah[2][4], al[2][4], bh[4][2], bl[4][2];
            const uint32_t kb = ks * 32 + lcol;
#pragma unroll
            for (int ms = 0; ms < 2; ++ms)
                ldsm4(ah[ms][0], ah[ms][1], ah[ms][2], ah[ms][3],
                      stg + OFF_AHI + (wm * 32 + ms * 16 + lrow) * 80 + kb);
#pragma unroll
            for (int p = 0; p < 2; ++p)
                ldsm4(bh[p * 2][0], bh[p * 2 + 1][0], bh[p * 2][1], bh[p * 2 + 1][1],
                      stg + OFF_BHI + (wn * 32 + p * 16 + lrow) * 80 + kb);
#pragma unroll
            for (int ms = 0; ms < 2; ++ms)
#pragma unroll
                for (int ns = 0; ns < 4; ++ns) hmma(acc[ms][ns], ah[ms], bh[ns]);
#pragma unroll
            for (int p = 0; p < 2; ++p)
                ldsm4(bl[p * 2][0], bl[p * 2 + 1][0], bl[p * 2][1], bl[p * 2 + 1][1],
                      stg + OFF_BLO + (wn * 32 + p * 16 + lrow) * 80 + kb);
#pragma unroll
            for (int ms = 0; ms < 2; ++ms)
#pragma unroll
                for (int ns = 0; ns < 4; ++ns) hmma(acc[ms][ns], ah[ms], bl[ns]);
#pragma unroll
            for (int ms = 0; ms < 2; ++ms)
                ldsm4(al[ms][0], al[ms][1], al[ms][2], al[ms][3],
                      stg + OFF_ALO + (wm * 32 + ms * 16 + lrow) * 80 + kb);
#pragma unroll
            for (int ms = 0; ms < 2; ++ms)
#pragma unroll
                for (int ns = 0; ns < 4; ++ns) hmma(acc[ms][ns], al[ms], bh[ns]);
        }
    }

    // ---------------- epilogue: bias + LayerNorm + ReLU (+ linear) ----------------
    float* partS = (float*)(smem + OFF_PART_S);   // [8][64]
    float* partQ = (float*)(smem + OFF_PART_Q);   // [8][64]
    float* meanA = (float*)(smem + OFF_MEAN);     // [64]
    float* rstdA = (float*)(smem + OFF_RSTD);     // [64]

    float2 bs[4], gm[4], bt[4], lwv[4];
#pragma unroll
    for (int ns = 0; ns < 4; ++ns) {
        int col = wn * 32 + ns * 8 + t4 * 2;
        bs[ns] = *(const float2*)(bias + col);
        gm[ns] = *(const float2*)(gam + col);
        bt[ns] = *(const float2*)(bet + col);
        if (DO_LIN) lwv[ns] = *(const float2*)(lw + col);
    }
#pragma unroll
    for (int ms = 0; ms < 2; ++ms)
#pragma unroll
        for (int ns = 0; ns < 4; ++ns) {
            acc[ms][ns][0] += bs[ns].x; acc[ms][ns][1] += bs[ns].y;
            acc[ms][ns][2] += bs[ns].x; acc[ms][ns][3] += bs[ns].y;
        }
    __syncthreads();   // mainloop smem reads done before stats-area writes
#pragma unroll
    for (int ms = 0; ms < 2; ++ms) {
        float s0 = 0.f, q0 = 0.f, s1 = 0.f, q1 = 0.f;
#pragma unroll
        for (int ns = 0; ns < 4; ++ns) {
            s0 += acc[ms][ns][0] + acc[ms][ns][1];
            q0 += acc[ms][ns][0] * acc[ms][ns][0] + acc[ms][ns][1] * acc[ms][ns][1];
            s1 += acc[ms][ns][2] + acc[ms][ns][3];
            q1 += acc[ms][ns][2] * acc[ms][ns][2] + acc[ms][ns][3] * acc[ms][ns][3];
        }
#pragma unroll
        for (int o = 1; o <= 2; o <<= 1) {
            s0 += __shfl_xor_sync(0xffffffffu, s0, o);
            q0 += __shfl_xor_sync(0xffffffffu, q0, o);
            s1 += __shfl_xor_sync(0xffffffffu, s1, o);
            q1 += __shfl_xor_sync(0xffffffffu, q1, o);
        }
        if (t4 == 0) {
            int r0 = wm * 32 + ms * 16 + g;
            partS[wn * 64 + r0] = s0;      partQ[wn * 64 + r0] = q0;
            partS[wn * 64 + r0 + 8] = s1;  partQ[wn * 64 + r0 + 8] = q1;
        }
    }
    __syncthreads();
    if (tid < 64) {
        float s = 0.f, q = 0.f;
#pragma unroll
        for (int w = 0; w < 8; ++w) { s += partS[w * 64 + tid]; q += partQ[w * 64 + tid]; }
        float mean = s * (1.f / 256.f);
        float var = q * (1.f / 256.f) - mean * mean;
        meanA[tid] = mean;
        rstdA[tid] = rsqrtf(var + EPS);
    }
    __syncthreads();

    float mu[2][2], rs[2][2];
#pragma unroll
    for (int ms = 0; ms < 2; ++ms)
#pragma unroll
        for (int h = 0; h < 2; ++h) {
            int lr = wm * 32 + ms * 16 + h * 8 + g;
            mu[ms][h] = meanA[lr];
            rs[ms][h] = rstdA[lr];
        }
    float y[2][4][4];
#pragma unroll
    for (int ms = 0; ms < 2; ++ms)
#pragma unroll
        for (int ns = 0; ns < 4; ++ns) {
            y[ms][ns][0] = fmaxf((acc[ms][ns][0] - mu[ms][0]) * rs[ms][0] * gm[ns].x + bt[ns].x, 0.f);
            y[ms][ns][1] = fmaxf((acc[ms][ns][1] - mu[ms][0]) * rs[ms][0] * gm[ns].y + bt[ns].y, 0.f);
            y[ms][ns][2] = fmaxf((acc[ms][ns][2] - mu[ms][1]) * rs[ms][1] * gm[ns].x + bt[ns].x, 0.f);
            y[ms][ns][3] = fmaxf((acc[ms][ns][3] - mu[ms][1]) * rs[ms][1] * gm[ns].y + bt[ns].y, 0.f);
        }

    if (!DO_LIN) {
#pragma unroll
        for (int ms = 0; ms < 2; ++ms)
#pragma unroll
            for (int h = 0; h < 2; ++h) {
                int grow = bm + wm * 32 + ms * 16 + h * 8 + g;
#pragma unroll
                for (int ns = 0; ns < 4; ++ns) {
                    int col = wn * 32 + ns * 8 + t4 * 2;
                    *(float2*)(out + (size_t)grow * FF + col) =
                        make_float2(y[ms][ns][h * 2], y[ms][ns][h * 2 + 1]);
                }
            }
    } else {
        __syncthreads();   // stats phase fully done before partS reuse
#pragma unroll
        for (int ms = 0; ms < 2; ++ms) {
            float p0 = 0.f, p1 = 0.f;
#pragma unroll
            for (int ns = 0; ns < 4; ++ns) {
                p0 += y[ms][ns][0] * lwv[ns].x + y[ms][ns][1] * lwv[ns].y;
                p1 += y[ms][ns][2] * lwv[ns].x + y[ms][ns][3] * lwv[ns].y;
            }
#pragma unroll
            for (int o = 1; o <= 2; o <<= 1) {
                p0 += __shfl_xor_sync(0xffffffffu, p0, o);
                p1 += __shfl_xor_sync(0xffffffffu, p1, o);
            }
            if (t4 == 0) {
                int r0 = wm * 32 + ms * 16 + g;
                partS[wn * 64 + r0] = p0;
                partS[wn * 64 + r0 + 8] = p1;
            }
        }
        __syncthreads();
        if (tid < 64) {
            float s = 0.f;
#pragma unroll
            for (int w = 0; w < 8; ++w) s += partS[w * 64 + tid];
            out[bm + tid] = fmaxf(s + lb[0], 0.f);
        }
    }
}

// ---------------- length regulation: index-lookup copy ----------------
__global__ void length_reg_kernel(const float* __restrict__ x,
                                  float* __restrict__ out) {
    unsigned tidg = blockIdx.x * 256u + threadIdx.x;  // over 16*4096*64 float4
    int c4 = tidg & 63;
    int nt = tidg >> 6;                  // n*4096 + t
    int l = __ldg(g_idx + nt);
    int n = nt >> 12;
    float4 v = make_float4(0.f, 0.f, 0.f, 0.f);
    if (l >= 0)
        v = *(const float4*)(x + ((n << 9) + l) * DD + c4 * 4);
    __stcs((float4*)(out + (size_t)tidg * 4), v);
}

// ---------------- launch ----------------
extern "C" void kernel_launch(void* const* d_in, const int* in_sizes, int n_in,
                              void* d_out, int out_size) {
    const float* x   = (const float*)d_in[0];
    const float* c1w = (const float*)d_in[1];
    const float* c1b = (const float*)d_in[2];
    const float* g1  = (const float*)d_in[3];
    const float* b1  = (const float*)d_in[4];
    const float* c2w = (const float*)d_in[5];
    const float* c2b = (const float*)d_in[6];
    const float* g2  = (const float*)d_in[7];
    const float* b2  = (const float*)d_in[8];
    const float* lw  = (const float*)d_in[9];
    const float* lb  = (const float*)d_in[10];
    const int*   tgt = (const int*)d_in[11];

    float* out = (float*)d_out;                         // [16,4096,256]
    float* dpo = out + (size_t)NB * TT * DD;            // [16,512]

    float* h1;
    __nv_bfloat16 *b1hi, *b1lo, *b2hi, *b2lo;
    cudaGetSymbolAddress((void**)&h1, g_h1);
    cudaGetSymbolAddress((void**)&b1hi, g_b1hi);
    cudaGetSymbolAddress((void**)&b1lo, g_b1lo);
    cudaGetSymbolAddress((void**)&b2hi, g_b2hi);
    cudaGetSymbolAddress((void**)&b2lo, g_b2lo);

    cudaFuncSetAttribute(conv_fused_kernel<false>,
                         cudaFuncAttributeMaxDynamicSharedMemorySize, SMEM_CONV);
    cudaFuncSetAttribute(conv_fused_kernel<true>,
                         cudaFuncAttributeMaxDynamicSharedMemorySize, SMEM_CONV);

    prep_b_cumsum_kernel<<<769, 256>>>(c1w, c2w, tgt);
    conv_fused_kernel<false><<<128, 512, SMEM_CONV>>>(x, b1hi, b1lo, c1b, g1, b1,
                                                      nullptr, nullptr, h1);
    conv_fused_kernel<true><<<128, 512, SMEM_CONV>>>(h1, b2hi, b2lo, c2b, g2, b2,
                                                     lw, lb, dpo);
    length_reg_kernel<<<(NB * TT * (DD / 4)) / 256, 256>>>(x, out);
}